// round 4
// baseline (speedup 1.0000x reference)
#include <cuda_runtime.h>

#define NN   8192
#define NCTA 128
#define NTHR 1024
#define WARPS_PER_CTA (NTHR / 32)          // 32
#define TOTAL_WARPS   (NCTA * WARPS_PER_CTA) // 4096
#define ROWS_PER_WARP (NN / TOTAL_WARPS)     // 2

// Scratch + barrier state (allocation-free rule: __device__ globals).
// Static-zero init; barrier protocol restores count=0, sense=0 at end of
// every launch -> deterministic across graph replays.
__device__ float g_conv[NN];
__device__ float g_h[NN];
__device__ int            g_count;
__device__ volatile int   g_sense;

__device__ __forceinline__ void grid_barrier(int target) {
    __syncthreads();
    if (threadIdx.x == 0) {
        __threadfence();                       // release my phase's stores
        if (atomicAdd(&g_count, 1) == NCTA - 1) {
            g_count = 0;                       // reset BEFORE flipping sense
            __threadfence();
            g_sense = target;
        } else {
            while (g_sense != target) { }
        }
        __threadfence();                       // acquire
    }
    __syncthreads();
}

// One warp computes two contiguous rows of y = act(W x + b).
__device__ __forceinline__ void mv_phase(const float* __restrict__ W,
                                         const float* __restrict__ bias,
                                         const float* __restrict__ x,
                                         float* __restrict__ y,
                                         bool do_tanh) {
    const int gw   = blockIdx.x * WARPS_PER_CTA + (threadIdx.x >> 5);
    const int lane = threadIdx.x & 31;
    const float4* __restrict__ x4 = reinterpret_cast<const float4*>(x);

    #pragma unroll
    for (int j = 0; j < ROWS_PER_WARP; ++j) {
        const int row = gw * ROWS_PER_WARP + j;
        const float4* __restrict__ W4 =
            reinterpret_cast<const float4*>(W + (size_t)row * NN);

        float s0 = 0.0f, s1 = 0.0f;
        // 2048 float4 per row / 32 lanes = 64 per lane
        #pragma unroll 8
        for (int k = 0; k < 64; k += 2) {
            int i0 = lane + 32 * k;
            int i1 = i0 + 32;
            float4 a0 = W4[i0];
            float4 v0 = x4[i0];
            float4 a1 = W4[i1];
            float4 v1 = x4[i1];
            s0 += a0.x * v0.x + a0.y * v0.y + a0.z * v0.z + a0.w * v0.w;
            s1 += a1.x * v1.x + a1.y * v1.y + a1.z * v1.z + a1.w * v1.w;
        }
        float s = s0 + s1;
        #pragma unroll
        for (int o = 16; o > 0; o >>= 1) s += __shfl_xor_sync(0xffffffffu, s, o);
        if (lane == 0) {
            s += bias[row];
            y[row] = do_tanh ? tanhf(s) : s;
        }
    }
}

__global__ void __launch_bounds__(NTHR, 1) fused_kernel(
    const float* __restrict__ nf,
    const float* __restrict__ cw,
    const float* __restrict__ cb,
    const float* __restrict__ W1,
    const float* __restrict__ b1,
    const float* __restrict__ W2,
    const float* __restrict__ b2,
    float* __restrict__ out) {

    // ---- Phase 1: conv + sigmoid (64 nodes per CTA, threads 0..63) ----
    {
        const int tid = threadIdx.x;
        if (tid < NN / NCTA) {
            const int i = blockIdx.x * (NN / NCTA) + tid;
            const float4* row = reinterpret_cast<const float4*>(nf + (size_t)i * 16);
            float4 w0 = reinterpret_cast<const float4*>(cw)[0];
            float4 w1 = reinterpret_cast<const float4*>(cw)[1];
            float4 w2 = reinterpret_cast<const float4*>(cw)[2];
            float4 w3 = reinterpret_cast<const float4*>(cw)[3];
            float4 a0 = row[0], a1 = row[1], a2 = row[2], a3 = row[3];
            float s = a0.x*w0.x + a0.y*w0.y + a0.z*w0.z + a0.w*w0.w
                    + a1.x*w1.x + a1.y*w1.y + a1.z*w1.z + a1.w*w1.w
                    + a2.x*w2.x + a2.y*w2.y + a2.z*w2.z + a2.w*w2.w
                    + a3.x*w3.x + a3.y*w3.y + a3.z*w3.z + a3.w*w3.w;
            s += cb[0];
            g_conv[i] = 1.0f / (1.0f + __expf(-s));
        }
    }

    grid_barrier(1);

    // ---- Phase 2: h = tanh(W1 . conv + b1) ----
    mv_phase(W1, b1, g_conv, g_h, true);

    grid_barrier(0);

    // ---- Phase 3: out = W2 . h + b2 ----
    mv_phase(W2, b2, g_h, out, false);
}

extern "C" void kernel_launch(void* const* d_in, const int* in_sizes, int n_in,
                              void* d_out, int out_size) {
    const float* node_features = (const float*)d_in[0]; // (8192, 16)
    const float* conv_w        = (const float*)d_in[1]; // (16,)
    const float* conv_b        = (const float*)d_in[2]; // scalar
    const float* W1            = (const float*)d_in[3]; // (8192, 8192)
    const float* b1            = (const float*)d_in[4]; // (8192,)
    const float* W2            = (const float*)d_in[5]; // (8192, 8192)
    const float* b2            = (const float*)d_in[6]; // (8192,)
    float* out = (float*)d_out;

    fused_kernel<<<NCTA, NTHR>>>(node_features, conv_w, conv_b,
                                 W1, b1, W2, b2, out);
}

// round 6
// speedup vs baseline: 1.0211x; 1.0211x over previous
#include <cuda_runtime.h>

#define NN 8192

// Scratch (allocation-free rule: __device__ globals)
__device__ float g_conv[NN];
__device__ float g_h[NN];

// Kernel 1: per-node 16-wide dot + bias + sigmoid
__global__ void __launch_bounds__(64) conv_sigmoid_kernel(
    const float* __restrict__ nf,
    const float* __restrict__ cw,
    const float* __restrict__ cb) {
    int i = blockIdx.x * 64 + threadIdx.x;
    if (i >= NN) return;
    const float4* row = reinterpret_cast<const float4*>(nf + (size_t)i * 16);
    float4 w0 = reinterpret_cast<const float4*>(cw)[0];
    float4 w1 = reinterpret_cast<const float4*>(cw)[1];
    float4 w2 = reinterpret_cast<const float4*>(cw)[2];
    float4 w3 = reinterpret_cast<const float4*>(cw)[3];
    float4 a0 = row[0], a1 = row[1], a2 = row[2], a3 = row[3];
    float s = a0.x*w0.x + a0.y*w0.y + a0.z*w0.z + a0.w*w0.w
            + a1.x*w1.x + a1.y*w1.y + a1.z*w1.z + a1.w*w1.w
            + a2.x*w2.x + a2.y*w2.y + a2.z*w2.z + a2.w*w2.w
            + a3.x*w3.x + a3.y*w3.y + a3.z*w3.z + a3.w*w3.w;
    s += cb[0];
    g_conv[i] = 1.0f / (1.0f + __expf(-s));
}

// Kernel 2/3: one row per 256-thread block. All 8 W float4 loads are
// front-batched into registers (MLP_p1 = 8 -> 32 cache lines in flight per
// warp) before any x-loads/FMAs, to maximize per-SM DRAM concurrency.
template <int APPLY_TANH>
__global__ void __launch_bounds__(256, 4) matvec_kernel(
    const float* __restrict__ W,
    const float* __restrict__ b,
    const float* __restrict__ x,
    float* __restrict__ y) {
    const int row = blockIdx.x;
    const int tid = threadIdx.x;
    const float4* __restrict__ W4 = reinterpret_cast<const float4*>(W + (size_t)row * NN);
    const float4* __restrict__ x4 = reinterpret_cast<const float4*>(x);

    // Front-batch: 8 x LDG.128 from W issued back-to-back
    float4 a[8];
    #pragma unroll
    for (int j = 0; j < 8; ++j) a[j] = W4[tid + 256 * j];

    // x loads are L1-resident after the first block on each SM
    float s = 0.0f;
    #pragma unroll
    for (int j = 0; j < 8; ++j) {
        float4 v = x4[tid + 256 * j];
        s += a[j].x * v.x + a[j].y * v.y + a[j].z * v.z + a[j].w * v.w;
    }

    // Block reduction: warp shuffle, then cross-warp via shared
    #pragma unroll
    for (int o = 16; o > 0; o >>= 1) s += __shfl_xor_sync(0xffffffffu, s, o);

    __shared__ float red[8];
    if ((tid & 31) == 0) red[tid >> 5] = s;
    __syncthreads();
    if (tid < 8) {
        s = red[tid];
        #pragma unroll
        for (int o = 4; o > 0; o >>= 1) s += __shfl_xor_sync(0x000000ffu, s, o);
        if (tid == 0) {
            s += b[row];
            y[row] = APPLY_TANH ? tanhf(s) : s;
        }
    }
}

extern "C" void kernel_launch(void* const* d_in, const int* in_sizes, int n_in,
                              void* d_out, int out_size) {
    const float* node_features = (const float*)d_in[0]; // (8192, 16)
    const float* conv_w        = (const float*)d_in[1]; // (16,)
    const float* conv_b        = (const float*)d_in[2]; // scalar
    const float* W1            = (const float*)d_in[3]; // (8192, 8192)
    const float* b1            = (const float*)d_in[4]; // (8192,)
    const float* W2            = (const float*)d_in[5]; // (8192, 8192)
    const float* b2            = (const float*)d_in[6]; // (8192,)
    float* out = (float*)d_out;

    float* conv_feats;
    float* h;
    cudaGetSymbolAddress((void**)&conv_feats, g_conv);
    cudaGetSymbolAddress((void**)&h, g_h);

    conv_sigmoid_kernel<<<NN / 64, 64>>>(node_features, conv_w, conv_b);
    matvec_kernel<1><<<NN, 256>>>(W1, b1, conv_feats, h);
    matvec_kernel<0><<<NN, 256>>>(W2, b2, h, out);
}

// round 7
// speedup vs baseline: 1.1709x; 1.1467x over previous
#include <cuda_runtime.h>
#include <cstdint>

#define NN 8192

// Scratch (allocation-free rule: __device__ globals)
__device__ float g_conv[NN];
__device__ float g_h[NN];

__device__ __forceinline__ void cp_async16(uint32_t smem_addr, const void* gptr) {
    asm volatile("cp.async.cg.shared.global [%0], [%1], 16;\n"
                 :: "r"(smem_addr), "l"(gptr));
}
__device__ __forceinline__ void cp_commit() {
    asm volatile("cp.async.commit_group;\n");
}
template <int N>
__device__ __forceinline__ void cp_wait() {
    asm volatile("cp.async.wait_group %0;\n" :: "n"(N));
}

// Kernel 1: per-node 16-wide dot + bias + sigmoid (small-kernel-floor bound)
__global__ void __launch_bounds__(64) conv_sigmoid_kernel(
    const float* __restrict__ nf,
    const float* __restrict__ cw,
    const float* __restrict__ cb) {
    int i = blockIdx.x * 64 + threadIdx.x;
    if (i >= NN) return;
    const float4* row = reinterpret_cast<const float4*>(nf + (size_t)i * 16);
    float4 w0 = reinterpret_cast<const float4*>(cw)[0];
    float4 w1 = reinterpret_cast<const float4*>(cw)[1];
    float4 w2 = reinterpret_cast<const float4*>(cw)[2];
    float4 w3 = reinterpret_cast<const float4*>(cw)[3];
    float4 a0 = row[0], a1 = row[1], a2 = row[2], a3 = row[3];
    float s = a0.x*w0.x + a0.y*w0.y + a0.z*w0.z + a0.w*w0.w
            + a1.x*w1.x + a1.y*w1.y + a1.z*w1.z + a1.w*w1.w
            + a2.x*w2.x + a2.y*w2.y + a2.z*w2.z + a2.w*w2.w
            + a3.x*w3.x + a3.y*w3.y + a3.z*w3.z + a3.w*w3.w;
    s += cb[0];
    g_conv[i] = 1.0f / (1.0f + __expf(-s));
}

// Kernel 2/3: one row per 256-thread block. The whole 32KB W row is pulled
// into shared via cp.async (zero register cost -> 32KB in flight per CTA,
// 6 CTAs/SM smem-bound occupancy -> ~190KB outstanding per SM). Each thread
// waits only on its own copies (reads back only its own slots), so no
// __syncthreads is needed. Two commit groups overlap the first half's
// compute with the second half's loads.
template <int APPLY_TANH>
__global__ void __launch_bounds__(256) matvec_kernel(
    const float* __restrict__ W,
    const float* __restrict__ b,
    const float* __restrict__ x,
    float* __restrict__ y) {
    __shared__ float4 buf[NN / 4];  // 32 KB

    const int row = blockIdx.x;
    const int tid = threadIdx.x;
    const float4* __restrict__ W4 = reinterpret_cast<const float4*>(W + (size_t)row * NN);
    const float4* __restrict__ x4 = reinterpret_cast<const float4*>(x);

    const uint32_t sbase = (uint32_t)__cvta_generic_to_shared(buf);

    // Issue all 8 copies (32KB/CTA in flight), split into two groups
    #pragma unroll
    for (int j = 0; j < 4; ++j) {
        int i = tid + 256 * j;
        cp_async16(sbase + i * 16, W4 + i);
    }
    cp_commit();
    #pragma unroll
    for (int j = 4; j < 8; ++j) {
        int i = tid + 256 * j;
        cp_async16(sbase + i * 16, W4 + i);
    }
    cp_commit();

    float s = 0.0f;

    cp_wait<1>();  // first group done
    #pragma unroll
    for (int j = 0; j < 4; ++j) {
        int i = tid + 256 * j;
        float4 a = buf[i];
        float4 v = x4[i];
        s += a.x * v.x + a.y * v.y + a.z * v.z + a.w * v.w;
    }

    cp_wait<0>();  // second group done
    #pragma unroll
    for (int j = 4; j < 8; ++j) {
        int i = tid + 256 * j;
        float4 a = buf[i];
        float4 v = x4[i];
        s += a.x * v.x + a.y * v.y + a.z * v.z + a.w * v.w;
    }

    // Block reduction: warp shuffle, then cross-warp via shared
    #pragma unroll
    for (int o = 16; o > 0; o >>= 1) s += __shfl_xor_sync(0xffffffffu, s, o);

    __shared__ float red[8];
    if ((tid & 31) == 0) red[tid >> 5] = s;
    __syncthreads();
    if (tid < 8) {
        s = red[tid];
        #pragma unroll
        for (int o = 4; o > 0; o >>= 1) s += __shfl_xor_sync(0x000000ffu, s, o);
        if (tid == 0) {
            s += b[row];
            y[row] = APPLY_TANH ? tanhf(s) : s;
        }
    }
}

extern "C" void kernel_launch(void* const* d_in, const int* in_sizes, int n_in,
                              void* d_out, int out_size) {
    const float* node_features = (const float*)d_in[0]; // (8192, 16)
    const float* conv_w        = (const float*)d_in[1]; // (16,)
    const float* conv_b        = (const float*)d_in[2]; // scalar
    const float* W1            = (const float*)d_in[3]; // (8192, 8192)
    const float* b1            = (const float*)d_in[4]; // (8192,)
    const float* W2            = (const float*)d_in[5]; // (8192, 8192)
    const float* b2            = (const float*)d_in[6]; // (8192,)
    float* out = (float*)d_out;

    float* conv_feats;
    float* h;
    cudaGetSymbolAddress((void**)&conv_feats, g_conv);
    cudaGetSymbolAddress((void**)&h, g_h);

    conv_sigmoid_kernel<<<NN / 64, 64>>>(node_features, conv_w, conv_b);
    matvec_kernel<1><<<NN, 256>>>(W1, b1, conv_feats, h);
    matvec_kernel<0><<<NN, 256>>>(W2, b2, h, out);
}